// round 2
// baseline (speedup 1.0000x reference)
#include <cuda_runtime.h>

#define SEQ   8192
#define DM    1024
#define DS    64
#define DI    128
#define NIT   50
#define NBLK  128
#define CHUNK 64
#define NTHR  256
#define DZX   1152   /* DI + DM */
#define DZHX  1216   /* DI + DS + DM */
#define PREW  256    /* lam(64) | u(64) | f(128) precomputed x-contributions */

// ---- static device scratch (no allocations allowed) ----
__device__ float g_pre[SEQ * PREW];            // 8 MB: x@Wx^T + biases
__device__ float g_agg[NIT * NBLK * 128];      // per-iteration chunk aggregates (Lam | U)
__device__ int   g_flag[NIT * NBLK];           // per-iteration readiness flags

__device__ __forceinline__ float sigmoidf_(float a) { return 1.0f / (1.0f + __expf(-a)); }
__device__ __forceinline__ float siluf_(float a)    { return a / (1.0f + __expf(-a)); }

__device__ __forceinline__ void fma8(float* a, float zv, float4 w0, float4 w1) {
    a[0] = fmaf(zv, w0.x, a[0]); a[1] = fmaf(zv, w0.y, a[1]);
    a[2] = fmaf(zv, w0.z, a[2]); a[3] = fmaf(zv, w0.w, a[3]);
    a[4] = fmaf(zv, w1.x, a[4]); a[5] = fmaf(zv, w1.y, a[5]);
    a[6] = fmaf(zv, w1.z, a[6]); a[7] = fmaf(zv, w1.w, a[7]);
}

// =====================================================================
// Precompute: g_pre = x @ [lam_wx; u_wx; f_wx]^T + [lam_b; u_b; f_b]
// Also clears the per-launch flags (runs before iter_kernel in-stream).
// =====================================================================
__global__ void __launch_bounds__(NTHR, 1)
pre_kernel(const float* __restrict__ x,
           const float* __restrict__ f_w, const float* __restrict__ f_b,
           const float* __restrict__ lam_w, const float* __restrict__ lam_b,
           const float* __restrict__ u_w, const float* __restrict__ u_b)
{
    for (int i = threadIdx.x + blockIdx.x * NTHR; i < NIT * NBLK; i += gridDim.x * NTHR)
        g_flag[i] = 0;

    extern __shared__ float sm[];
    float* xs = sm;            // [64][128]
    float* wt = sm + 64 * 128; // [128][256] k-major

    const int tid = threadIdx.x;
    const int t0 = blockIdx.x * CHUNK;
    const int ox = tid & 15;
    const int ty = tid >> 4;
    const int tA = ty * 4;

    float acc[4][16];
    #pragma unroll
    for (int i = 0; i < 4; i++)
        #pragma unroll
        for (int j = 0; j < 16; j++) acc[i][j] = 0.f;

    // staging source row for o = tid
    const float* wsrc;
    {
        int o = tid;
        if (o < 64)       wsrc = lam_w + o * DZX + DI;
        else if (o < 128) wsrc = u_w + (o - 64) * DZX + DI;
        else              wsrc = f_w + (o - 128) * DZHX + DI + DS;
    }

    #pragma unroll 1
    for (int kt = 0; kt < DM; kt += 128) {
        __syncthreads();
        for (int i = tid; i < 64 * 32; i += NTHR) {
            int r = i >> 5, c4 = (i & 31) << 2;
            *(float4*)(xs + r * 128 + c4) = *(const float4*)(x + (t0 + r) * DM + kt + c4);
        }
        {
            const float* s = wsrc + kt;
            #pragma unroll
            for (int k4 = 0; k4 < 32; k4++) {
                float4 v = *(const float4*)(s + k4 * 4);
                int k = k4 * 4;
                wt[(k + 0) * 256 + tid] = v.x;
                wt[(k + 1) * 256 + tid] = v.y;
                wt[(k + 2) * 256 + tid] = v.z;
                wt[(k + 3) * 256 + tid] = v.w;
            }
        }
        __syncthreads();
        #pragma unroll 1
        for (int k = 0; k < 128; k += 4) {
            float4 xr[4];
            #pragma unroll
            for (int i = 0; i < 4; i++)
                xr[i] = *(const float4*)(xs + (tA + i) * 128 + k);
            #pragma unroll
            for (int kk = 0; kk < 4; kk++) {
                float4 w[4];
                #pragma unroll
                for (int g = 0; g < 4; g++)
                    w[g] = *(const float4*)(wt + (k + kk) * 256 + g * 64 + ox * 4);
                #pragma unroll
                for (int i = 0; i < 4; i++) {
                    float xv = ((const float*)&xr[i])[kk];
                    #pragma unroll
                    for (int g = 0; g < 4; g++) {
                        acc[i][g*4+0] = fmaf(xv, w[g].x, acc[i][g*4+0]);
                        acc[i][g*4+1] = fmaf(xv, w[g].y, acc[i][g*4+1]);
                        acc[i][g*4+2] = fmaf(xv, w[g].z, acc[i][g*4+2]);
                        acc[i][g*4+3] = fmaf(xv, w[g].w, acc[i][g*4+3]);
                    }
                }
            }
        }
    }
    // bias + store
    #pragma unroll
    for (int g = 0; g < 4; g++)
        #pragma unroll
        for (int e = 0; e < 4; e++) {
            int o = g * 64 + ox * 4 + e;
            float bb = (o < 64) ? lam_b[o] : (o < 128 ? u_b[o - 64] : f_b[o - 128]);
            #pragma unroll
            for (int i = 0; i < 4; i++) acc[i][g*4+e] += bb;
        }
    #pragma unroll
    for (int i = 0; i < 4; i++) {
        float* dst = g_pre + (size_t)(t0 + tA + i) * PREW;
        #pragma unroll
        for (int g = 0; g < 4; g++)
            *(float4*)(dst + g * 64 + ox * 4) =
                make_float4(acc[i][g*4+0], acc[i][g*4+1], acc[i][g*4+2], acc[i][g*4+3]);
    }
}

// =====================================================================
// Persistent kernel: 50 fixed-point iterations + output projection.
// 128 blocks x 64 tokens; z lives in smem; cross-block coupling is ONLY
// the scan prefix (decoupled lookback with per-iteration flag slots).
// =====================================================================
__global__ void __launch_bounds__(NTHR, 1)
iter_kernel(const float* __restrict__ f_w,
            const float* __restrict__ lam_w,
            const float* __restrict__ u_w,
            const float* __restrict__ out_w,
            const float* __restrict__ out_b,
            float* __restrict__ out)
{
    extern __shared__ float sm[];
    float* z_s   = sm;                 // [64][128]
    float* wA    = z_s + 64 * 128;     // [128][128] k-major (o<64: lam_wz, o>=64: u_wz)
    float* fz    = wA + 128 * 128;     // [128][128] k-major f_wz
    float* fh    = fz + 128 * 128;     // [64][128]  c-major f_wh
    float* lam_s = fh + 64 * 128;      // [64][64]   lam -> prefix product
    float* u_s   = lam_s + 64 * 64;    // [64][64]   u -> local h -> shifted h

    const int tid = threadIdx.x;
    const int b   = blockIdx.x;
    const int t0  = b * CHUNK;
    const int ox  = tid & 15;
    const int ty  = tid >> 4;
    const int tA  = ty * 4;

    // ---- stage weights transposed (once) ----
    {
        int o  = tid >> 1;
        int kh = (tid & 1) * 64;
        const float* sA = (o < 64) ? (lam_w + o * DZX) : (u_w + (o - 64) * DZX);
        const float* sF = f_w + o * DZHX;
        #pragma unroll
        for (int k4 = 0; k4 < 16; k4++) {
            int k = kh + k4 * 4;
            float4 a = *(const float4*)(sA + k);
            wA[(k+0)*128 + o] = a.x; wA[(k+1)*128 + o] = a.y;
            wA[(k+2)*128 + o] = a.z; wA[(k+3)*128 + o] = a.w;
            float4 f = *(const float4*)(sF + k);
            fz[(k+0)*128 + o] = f.x; fz[(k+1)*128 + o] = f.y;
            fz[(k+2)*128 + o] = f.z; fz[(k+3)*128 + o] = f.w;
        }
        int ch = (tid & 1) * 32;
        #pragma unroll
        for (int c4 = 0; c4 < 8; c4++) {
            int c = ch + c4 * 4;
            float4 f = *(const float4*)(sF + DI + c);
            fh[(c+0)*128 + o] = f.x; fh[(c+1)*128 + o] = f.y;
            fh[(c+2)*128 + o] = f.z; fh[(c+3)*128 + o] = f.w;
        }
    }
    for (int i = tid; i < CHUNK * DI; i += NTHR) z_s[i] = 0.f;
    __syncthreads();

    #pragma unroll 1
    for (int it = 0; it < NIT; ++it) {
        // ================= Phase A: lam/u pre-activations =================
        float acc[4][8];
        #pragma unroll
        for (int i = 0; i < 4; i++) {
            const float* pr = g_pre + (size_t)(t0 + tA + i) * PREW;
            float4 a0 = *(const float4*)(pr + ox * 4);
            float4 a1 = *(const float4*)(pr + 64 + ox * 4);
            acc[i][0]=a0.x; acc[i][1]=a0.y; acc[i][2]=a0.z; acc[i][3]=a0.w;
            acc[i][4]=a1.x; acc[i][5]=a1.y; acc[i][6]=a1.z; acc[i][7]=a1.w;
        }
        #pragma unroll 1
        for (int k = 0; k < DI; k += 4) {
            float4 zr[4];
            #pragma unroll
            for (int i = 0; i < 4; i++)
                zr[i] = *(const float4*)(z_s + (tA + i) * DI + k);
            #pragma unroll
            for (int kk = 0; kk < 4; kk++) {
                float4 w0 = *(const float4*)(wA + (k + kk) * 128 + ox * 4);
                float4 w1 = *(const float4*)(wA + (k + kk) * 128 + 64 + ox * 4);
                #pragma unroll
                for (int i = 0; i < 4; i++)
                    fma8(acc[i], ((const float*)&zr[i])[kk], w0, w1);
            }
        }
        #pragma unroll
        for (int i = 0; i < 4; i++) {
            int t = tA + i;
            *(float4*)(lam_s + t * DS + ox * 4) =
                make_float4(sigmoidf_(acc[i][0]), sigmoidf_(acc[i][1]),
                            sigmoidf_(acc[i][2]), sigmoidf_(acc[i][3]));
            *(float4*)(u_s + t * DS + ox * 4) =
                make_float4(acc[i][4], acc[i][5], acc[i][6], acc[i][7]);
        }
        __syncthreads();

        // ================= local scan + publish aggregate; others pre-spin =================
        if (tid < DS) {
            int c = tid;
            float P = 1.f, H = 0.f;
            #pragma unroll 8
            for (int t = 0; t < CHUNK; t++) {
                float l  = lam_s[t * DS + c];
                float uu = u_s[t * DS + c];
                H = fmaf(l, H, uu);
                P *= l;
                lam_s[t * DS + c] = P;   // prefix product
                u_s[t * DS + c]   = H;   // local inclusive h
            }
            float* ag = g_agg + (size_t)(it * NBLK + b) * 128;
            ag[c]      = P;
            ag[c + 64] = H;
            __threadfence();
            asm volatile("bar.sync 1, 64;");
            if (tid == 0)
                *(volatile int*)(g_flag + it * NBLK + b) = 1;
        } else {
            int j = tid - 64;
            if (j < b) {
                volatile int* fl = g_flag + it * NBLK + j;
                while (*fl == 0) { }
            }
        }
        __syncthreads();

        // ================= lookback fold + apply + shift =================
        if (tid < DS) {
            int c = tid;
            float h = 0.f;
            const float* ag = g_agg + (size_t)it * NBLK * 128 + c;
            #pragma unroll 4
            for (int j = 0; j < b; j++)
                h = fmaf(ag[j * 128], h, ag[j * 128 + 64]);   // chunk-ordered fold
            float prev = h;                                    // h entering this chunk
            #pragma unroll 8
            for (int t = 0; t < CHUNK; t++) {
                float P  = lam_s[t * DS + c];
                float Hl = u_s[t * DS + c];
                float hg = fmaf(P, h, Hl);                     // global inclusive h_t
                u_s[t * DS + c] = prev;                        // shifted: h used at t
                prev = hg;
            }
        }
        __syncthreads();

        // ================= Phase C: z_new = silu(f_x + f_wz@z + f_wh@h) =================
        float acc2[4][8];
        #pragma unroll
        for (int i = 0; i < 4; i++) {
            const float* pr = g_pre + (size_t)(t0 + tA + i) * PREW + 128;
            float4 a0 = *(const float4*)(pr + ox * 4);
            float4 a1 = *(const float4*)(pr + 64 + ox * 4);
            acc2[i][0]=a0.x; acc2[i][1]=a0.y; acc2[i][2]=a0.z; acc2[i][3]=a0.w;
            acc2[i][4]=a1.x; acc2[i][5]=a1.y; acc2[i][6]=a1.z; acc2[i][7]=a1.w;
        }
        #pragma unroll 1
        for (int k = 0; k < DI; k += 4) {
            float4 zr[4];
            #pragma unroll
            for (int i = 0; i < 4; i++)
                zr[i] = *(const float4*)(z_s + (tA + i) * DI + k);
            #pragma unroll
            for (int kk = 0; kk < 4; kk++) {
                float4 w0 = *(const float4*)(fz + (k + kk) * 128 + ox * 4);
                float4 w1 = *(const float4*)(fz + (k + kk) * 128 + 64 + ox * 4);
                #pragma unroll
                for (int i = 0; i < 4; i++)
                    fma8(acc2[i], ((const float*)&zr[i])[kk], w0, w1);
            }
        }
        #pragma unroll 1
        for (int c = 0; c < DS; c += 4) {
            float4 hr[4];
            #pragma unroll
            for (int i = 0; i < 4; i++)
                hr[i] = *(const float4*)(u_s + (tA + i) * DS + c);
            #pragma unroll
            for (int cc = 0; cc < 4; cc++) {
                float4 w0 = *(const float4*)(fh + (c + cc) * 128 + ox * 4);
                float4 w1 = *(const float4*)(fh + (c + cc) * 128 + 64 + ox * 4);
                #pragma unroll
                for (int i = 0; i < 4; i++)
                    fma8(acc2[i], ((const float*)&hr[i])[cc], w0, w1);
            }
        }
        __syncthreads();   // all reads of z_s complete before overwrite
        #pragma unroll
        for (int i = 0; i < 4; i++) {
            int t = tA + i;
            *(float4*)(z_s + t * DI + ox * 4) =
                make_float4(siluf_(acc2[i][0]), siluf_(acc2[i][1]),
                            siluf_(acc2[i][2]), siluf_(acc2[i][3]));
            *(float4*)(z_s + t * DI + 64 + ox * 4) =
                make_float4(siluf_(acc2[i][4]), siluf_(acc2[i][5]),
                            siluf_(acc2[i][6]), siluf_(acc2[i][7]));
        }
        __syncthreads();
    }

    // ================= output projection: out = z @ out_w^T + out_b =================
    float* wt = wA;  // reuse wA+fz region: [128][256] = 32768 floats
    #pragma unroll 1
    for (int mc = 0; mc < DM; mc += 256) {
        __syncthreads();
        {
            const float* src = out_w + (size_t)(mc + tid) * DI;
            #pragma unroll
            for (int k4 = 0; k4 < 32; k4++) {
                float4 v = *(const float4*)(src + k4 * 4);
                int k = k4 * 4;
                wt[(k+0)*256 + tid] = v.x;
                wt[(k+1)*256 + tid] = v.y;
                wt[(k+2)*256 + tid] = v.z;
                wt[(k+3)*256 + tid] = v.w;
            }
        }
        __syncthreads();
        float acc3[4][16];
        #pragma unroll
        for (int g = 0; g < 4; g++)
            #pragma unroll
            for (int e = 0; e < 4; e++) {
                float bb = out_b[mc + g * 64 + ox * 4 + e];
                #pragma unroll
                for (int i = 0; i < 4; i++) acc3[i][g*4+e] = bb;
            }
        #pragma unroll 1
        for (int k = 0; k < DI; k += 4) {
            float4 zr[4];
            #pragma unroll
            for (int i = 0; i < 4; i++)
                zr[i] = *(const float4*)(z_s + (tA + i) * DI + k);
            #pragma unroll
            for (int kk = 0; kk < 4; kk++) {
                float4 w[4];
                #pragma unroll
                for (int g = 0; g < 4; g++)
                    w[g] = *(const float4*)(wt + (k + kk) * 256 + g * 64 + ox * 4);
                #pragma unroll
                for (int i = 0; i < 4; i++) {
                    float zv = ((const float*)&zr[i])[kk];
                    #pragma unroll
                    for (int g = 0; g < 4; g++) {
                        acc3[i][g*4+0] = fmaf(zv, w[g].x, acc3[i][g*4+0]);
                        acc3[i][g*4+1] = fmaf(zv, w[g].y, acc3[i][g*4+1]);
                        acc3[i][g*4+2] = fmaf(zv, w[g].z, acc3[i][g*4+2]);
                        acc3[i][g*4+3] = fmaf(zv, w[g].w, acc3[i][g*4+3]);
                    }
                }
            }
        }
        #pragma unroll
        for (int i = 0; i < 4; i++) {
            float* dst = out + (size_t)(t0 + tA + i) * DM + mc;
            #pragma unroll
            for (int g = 0; g < 4; g++)
                *(float4*)(dst + g * 64 + ox * 4) =
                    make_float4(acc3[i][g*4+0], acc3[i][g*4+1],
                                acc3[i][g*4+2], acc3[i][g*4+3]);
        }
    }
}

#define PRE_SMEM  ((64 * 128 + 128 * 256) * 4)                 /* 160 KB */
#define ITER_SMEM ((64*128 + 128*128 + 128*128 + 64*128 + 64*64 + 64*64) * 4) /* 224 KB */

extern "C" void kernel_launch(void* const* d_in, const int* in_sizes, int n_in,
                              void* d_out, int out_size) {
    const float* x     = (const float*)d_in[0];
    const float* f_w   = (const float*)d_in[1];
    const float* f_b   = (const float*)d_in[2];
    const float* lam_w = (const float*)d_in[3];
    const float* lam_b = (const float*)d_in[4];
    const float* u_w   = (const float*)d_in[5];
    const float* u_b   = (const float*)d_in[6];
    const float* out_w = (const float*)d_in[7];
    const float* out_b = (const float*)d_in[8];
    float* out = (float*)d_out;

    cudaFuncSetAttribute(pre_kernel,  cudaFuncAttributeMaxDynamicSharedMemorySize, PRE_SMEM);
    cudaFuncSetAttribute(iter_kernel, cudaFuncAttributeMaxDynamicSharedMemorySize, ITER_SMEM);

    pre_kernel<<<NBLK, NTHR, PRE_SMEM>>>(x, f_w, f_b, lam_w, lam_b, u_w, u_b);
    iter_kernel<<<NBLK, NTHR, ITER_SMEM>>>(f_w, lam_w, u_w, out_w, out_b, out);
}

// round 4
// speedup vs baseline: 1.3428x; 1.3428x over previous
#include <cuda_runtime.h>

#define SEQ   8192
#define DM    1024
#define DS    64
#define DI    128
#define NIT   50
#define NBLK  128
#define CHUNK 64
#define NTHR  512
#define DZX   1152   /* DI + DM */
#define DZHX  1216   /* DI + DS + DM */
#define PREW  256    /* lam(64) | u(64) | f(128) precomputed x-contributions */

// ---- static device scratch (no allocations allowed) ----
__device__ float g_pre[SEQ * PREW];            // 8 MB: x@Wx^T + biases
__device__ float g_agg[NIT * NBLK * 128];      // per-iteration chunk aggregates (Lam | U)
__device__ int   g_flag[NIT * NBLK];           // per-iteration readiness flags

__device__ __forceinline__ float sigmoidf_(float a) { return 1.0f / (1.0f + __expf(-a)); }
__device__ __forceinline__ float siluf_(float a)    { return a / (1.0f + __expf(-a)); }

// ---- packed fp32x2 helpers (FFMA2 path; exact fp32 semantics) ----
__device__ __forceinline__ unsigned long long pack2(float v) {
    unsigned long long r;
    asm("mov.b64 %0, {%1, %1};" : "=l"(r) : "r"(__float_as_uint(v)));
    return r;
}
__device__ __forceinline__ void ffma2(unsigned long long& d,
                                      unsigned long long a, unsigned long long b) {
    asm("fma.rn.f32x2 %0, %1, %2, %0;" : "+l"(d) : "l"(a), "l"(b));
}
__device__ __forceinline__ float2 unpack2(unsigned long long v) {
    float2 r;
    unsigned lo, hi;
    asm("mov.b64 {%0, %1}, %2;" : "=r"(lo), "=r"(hi) : "l"(v));
    r.x = __uint_as_float(lo); r.y = __uint_as_float(hi);
    return r;
}

// acc[0..3] += z * w[ox*4 .. ox*4+3 | 64+ox*4 .. 64+ox*4+3]   (8 outputs, split layout)
__device__ __forceinline__ void fma8p(unsigned long long* a, unsigned long long zz,
                                      const float* wrow, int ox) {
    ulonglong2 w0 = *(const ulonglong2*)(wrow + ox * 4);
    ulonglong2 w1 = *(const ulonglong2*)(wrow + 64 + ox * 4);
    ffma2(a[0], zz, w0.x); ffma2(a[1], zz, w0.y);
    ffma2(a[2], zz, w1.x); ffma2(a[3], zz, w1.y);
}
// acc[0..7] += z * w[g*64 + ox*4 ...] for g=0..3   (16 outputs over 256-wide row)
__device__ __forceinline__ void fma16p(unsigned long long* a, unsigned long long zz,
                                       const float* wrow, int ox) {
    #pragma unroll
    for (int g = 0; g < 4; g++) {
        ulonglong2 w = *(const ulonglong2*)(wrow + g * 64 + ox * 4);
        ffma2(a[g*2+0], zz, w.x);
        ffma2(a[g*2+1], zz, w.y);
    }
}

// =====================================================================
// Precompute: g_pre = x @ [lam_wx; u_wx; f_wx]^T + [lam_b; u_b; f_b]
// Also clears the per-launch flags (runs before iter_kernel in-stream).
// =====================================================================
__global__ void __launch_bounds__(NTHR, 1)
pre_kernel(const float* __restrict__ x,
           const float* __restrict__ f_w, const float* __restrict__ f_b,
           const float* __restrict__ lam_w, const float* __restrict__ lam_b,
           const float* __restrict__ u_w, const float* __restrict__ u_b)
{
    for (int i = threadIdx.x + blockIdx.x * NTHR; i < NIT * NBLK; i += gridDim.x * NTHR)
        g_flag[i] = 0;

    extern __shared__ float sm[];
    float* xs = sm;            // [64][128]
    float* wt = sm + 64 * 128; // [128][256] k-major

    const int tid = threadIdx.x;
    const int t0 = blockIdx.x * CHUNK;
    const int ox = tid & 15;       // 16 output groups of 16
    const int ty = tid >> 4;       // 32 token groups of 2
    const int tA = ty * 2;

    unsigned long long acc[2][8];
    #pragma unroll
    for (int i = 0; i < 2; i++)
        #pragma unroll
        for (int j = 0; j < 8; j++) acc[i][j] = 0ull;

    // staging: o = tid>>1 (0..255), half picks 64 of 128 k-cols of this tile
    const int o    = tid >> 1;
    const int half = (tid & 1) * 64;
    const float* wsrc;
    if (o < 64)       wsrc = lam_w + o * DZX + DI;
    else if (o < 128) wsrc = u_w + (o - 64) * DZX + DI;
    else              wsrc = f_w + (o - 128) * DZHX + DI + DS;

    #pragma unroll 1
    for (int kt = 0; kt < DM; kt += 128) {
        __syncthreads();
        for (int i = tid; i < 64 * 32; i += NTHR) {
            int r = i >> 5, c4 = (i & 31) << 2;
            *(float4*)(xs + r * 128 + c4) = *(const float4*)(x + (t0 + r) * DM + kt + c4);
        }
        #pragma unroll
        for (int k4 = 0; k4 < 16; k4++) {
            int k = half + k4 * 4;
            float4 v = *(const float4*)(wsrc + kt + k);
            wt[(k + 0) * 256 + o] = v.x;
            wt[(k + 1) * 256 + o] = v.y;
            wt[(k + 2) * 256 + o] = v.z;
            wt[(k + 3) * 256 + o] = v.w;
        }
        __syncthreads();
        #pragma unroll 1
        for (int k = 0; k < 128; k += 4) {
            float4 zr0 = *(const float4*)(xs + (tA + 0) * 128 + k);
            float4 zr1 = *(const float4*)(xs + (tA + 1) * 128 + k);
            #pragma unroll
            for (int kk = 0; kk < 4; kk++) {
                const float* wrow = wt + (k + kk) * 256;
                fma16p(acc[0], pack2(((const float*)&zr0)[kk]), wrow, ox);
                fma16p(acc[1], pack2(((const float*)&zr1)[kk]), wrow, ox);
            }
        }
    }
    // bias + store
    #pragma unroll
    for (int i = 0; i < 2; i++) {
        float* dst = g_pre + (size_t)(t0 + tA + i) * PREW;
        #pragma unroll
        for (int g = 0; g < 4; g++) {
            float2 lo = unpack2(acc[i][g*2+0]);
            float2 hi = unpack2(acc[i][g*2+1]);
            int o0 = g * 64 + ox * 4;
            float b0, b1, b2, b3;
            if (o0 < 64)       { b0=lam_b[o0]; b1=lam_b[o0+1]; b2=lam_b[o0+2]; b3=lam_b[o0+3]; }
            else if (o0 < 128) { b0=u_b[o0-64]; b1=u_b[o0-63]; b2=u_b[o0-62]; b3=u_b[o0-61]; }
            else               { b0=f_b[o0-128]; b1=f_b[o0-127]; b2=f_b[o0-126]; b3=f_b[o0-125]; }
            *(float4*)(dst + o0) = make_float4(lo.x + b0, lo.y + b1, hi.x + b2, hi.y + b3);
        }
    }
}

// =====================================================================
// Persistent kernel: 50 fixed-point iterations + output projection.
// 128 blocks x 64 tokens; z lives in smem; cross-block coupling is ONLY
// the scan prefix (decoupled lookback with per-iteration flag slots).
// =====================================================================
__global__ void __launch_bounds__(NTHR, 1)
iter_kernel(const float* __restrict__ f_w,
            const float* __restrict__ lam_w,
            const float* __restrict__ u_w,
            const float* __restrict__ out_w,
            const float* __restrict__ out_b,
            float* __restrict__ out)
{
    extern __shared__ float sm[];
    float* z_s   = sm;                 // [64][128]
    float* wA    = z_s + 64 * 128;     // [128][128] k-major (o<64: lam_wz, o>=64: u_wz)
    float* fz    = wA + 128 * 128;     // [128][128] k-major f_wz
    float* fh    = fz + 128 * 128;     // [64][128]  c-major f_wh
    float* lam_s = fh + 64 * 128;      // [64][64]   lam -> prefix product
    float* u_s   = lam_s + 64 * 64;    // [64][64]   u -> local h -> shifted h

    const int tid = threadIdx.x;
    const int b   = blockIdx.x;
    const int t0  = b * CHUNK;
    const int ox  = tid & 15;          // 16 output groups of 8 (split 4+4)
    const int ty  = tid >> 4;          // 32 token groups of 2
    const int tA  = ty * 2;

    // ---- stage weights transposed (once) ----
    {
        int o    = tid >> 2;          // 0..127
        int part = tid & 3;           // k quarter
        const float* sA = (o < 64) ? (lam_w + o * DZX) : (u_w + (o - 64) * DZX);
        const float* sF = f_w + o * DZHX;
        #pragma unroll
        for (int k4 = 0; k4 < 8; k4++) {
            int k = part * 32 + k4 * 4;
            float4 a = *(const float4*)(sA + k);
            wA[(k+0)*128 + o] = a.x; wA[(k+1)*128 + o] = a.y;
            wA[(k+2)*128 + o] = a.z; wA[(k+3)*128 + o] = a.w;
            float4 f = *(const float4*)(sF + k);
            fz[(k+0)*128 + o] = f.x; fz[(k+1)*128 + o] = f.y;
            fz[(k+2)*128 + o] = f.z; fz[(k+3)*128 + o] = f.w;
        }
        if (part < 2) {
            #pragma unroll
            for (int c4 = 0; c4 < 8; c4++) {
                int c = part * 32 + c4 * 4;
                float4 f = *(const float4*)(sF + DI + c);
                fh[(c+0)*128 + o] = f.x; fh[(c+1)*128 + o] = f.y;
                fh[(c+2)*128 + o] = f.z; fh[(c+3)*128 + o] = f.w;
            }
        }
    }
    for (int i = tid; i < CHUNK * DI; i += NTHR) z_s[i] = 0.f;
    __syncthreads();

    #pragma unroll 1
    for (int it = 0; it < NIT; ++it) {
        // ================= Phase A: lam/u pre-activations =================
        unsigned long long acc[2][4];
        #pragma unroll
        for (int i = 0; i < 2; i++) {
            const float* pr = g_pre + (size_t)(t0 + tA + i) * PREW;
            ulonglong2 a0 = *(const ulonglong2*)(pr + ox * 4);
            ulonglong2 a1 = *(const ulonglong2*)(pr + 64 + ox * 4);
            acc[i][0] = a0.x; acc[i][1] = a0.y;
            acc[i][2] = a1.x; acc[i][3] = a1.y;
        }
        #pragma unroll 1
        for (int k = 0; k < DI; k += 4) {
            float4 zr0 = *(const float4*)(z_s + (tA + 0) * DI + k);
            float4 zr1 = *(const float4*)(z_s + (tA + 1) * DI + k);
            #pragma unroll
            for (int kk = 0; kk < 4; kk++) {
                const float* wrow = wA + (k + kk) * 128;
                fma8p(acc[0], pack2(((const float*)&zr0)[kk]), wrow, ox);
                fma8p(acc[1], pack2(((const float*)&zr1)[kk]), wrow, ox);
            }
        }
        #pragma unroll
        for (int i = 0; i < 2; i++) {
            int t = tA + i;
            float2 l0 = unpack2(acc[i][0]), l1 = unpack2(acc[i][1]);
            float2 v0 = unpack2(acc[i][2]), v1 = unpack2(acc[i][3]);
            *(float4*)(lam_s + t * DS + ox * 4) =
                make_float4(sigmoidf_(l0.x), sigmoidf_(l0.y),
                            sigmoidf_(l1.x), sigmoidf_(l1.y));
            *(float4*)(u_s + t * DS + ox * 4) = make_float4(v0.x, v0.y, v1.x, v1.y);
        }
        __syncthreads();

        // ================= local scan + publish aggregate; others pre-spin =================
        if (tid < DS) {
            int c = tid;
            float P = 1.f, H = 0.f;
            #pragma unroll 8
            for (int t = 0; t < CHUNK; t++) {
                float l  = lam_s[t * DS + c];
                float uu = u_s[t * DS + c];
                H = fmaf(l, H, uu);
                P *= l;
                lam_s[t * DS + c] = P;   // prefix product
                u_s[t * DS + c]   = H;   // local inclusive h
            }
            float* ag = g_agg + (size_t)(it * NBLK + b) * 128;
            ag[c]      = P;
            ag[c + 64] = H;
            __threadfence();
            asm volatile("bar.sync 1, 64;");
            if (tid == 0)
                *(volatile int*)(g_flag + it * NBLK + b) = 1;
        } else {
            int j = tid - 64;
            if (j < b) {
                volatile int* fl = g_flag + it * NBLK + j;
                while (*fl == 0) { }
            }
        }
        __syncthreads();

        // ================= lookback fold + apply + shift =================
        if (tid < DS) {
            int c = tid;
            float h = 0.f;
            const float* ag = g_agg + (size_t)it * NBLK * 128 + c;
            #pragma unroll 4
            for (int j = 0; j < b; j++)
                h = fmaf(ag[j * 128], h, ag[j * 128 + 64]);   // chunk-ordered fold
            float prev = h;                                    // h entering this chunk
            #pragma unroll 8
            for (int t = 0; t < CHUNK; t++) {
                float P  = lam_s[t * DS + c];
                float Hl = u_s[t * DS + c];
                float hg = fmaf(P, h, Hl);                     // global inclusive h_t
                u_s[t * DS + c] = prev;                        // shifted: h used at t
                prev = hg;
            }
        }
        __syncthreads();

        // ================= Phase C: z_new = silu(f_x + f_wz@z + f_wh@h) =================
        unsigned long long acc2[2][4];
        #pragma unroll
        for (int i = 0; i < 2; i++) {
            const float* pr = g_pre + (size_t)(t0 + tA + i) * PREW + 128;
            ulonglong2 a0 = *(const ulonglong2*)(pr + ox * 4);
            ulonglong2 a1 = *(const ulonglong2*)(pr + 64 + ox * 4);
            acc2[i][0] = a0.x; acc2[i][1] = a0.y;
            acc2[i][2] = a1.x; acc2[i][3] = a1.y;
        }
        #pragma unroll 1
        for (int k = 0; k < DI; k += 4) {
            float4 zr0 = *(const float4*)(z_s + (tA + 0) * DI + k);
            float4 zr1 = *(const float4*)(z_s + (tA + 1) * DI + k);
            #pragma unroll
            for (int kk = 0; kk < 4; kk++) {
                const float* wrow = fz + (k + kk) * 128;
                fma8p(acc2[0], pack2(((const float*)&zr0)[kk]), wrow, ox);
                fma8p(acc2[1], pack2(((const float*)&zr1)[kk]), wrow, ox);
            }
        }
        #pragma unroll 1
        for (int c = 0; c < DS; c += 4) {
            float4 hr0 = *(const float4*)(u_s + (tA + 0) * DS + c);
            float4 hr1 = *(const float4*)(u_s + (tA + 1) * DS + c);
            #pragma unroll
            for (int cc = 0; cc < 4; cc++) {
                const float* wrow = fh + (c + cc) * 128;
                fma8p(acc2[0], pack2(((const float*)&hr0)[cc]), wrow, ox);
                fma8p(acc2[1], pack2(((const float*)&hr1)[cc]), wrow, ox);
            }
        }
        __syncthreads();   // all reads of z_s complete before overwrite
        #pragma unroll
        for (int i = 0; i < 2; i++) {
            int t = tA + i;
            float2 a0 = unpack2(acc2[i][0]), a1 = unpack2(acc2[i][1]);
            float2 a2 = unpack2(acc2[i][2]), a3 = unpack2(acc2[i][3]);
            *(float4*)(z_s + t * DI + ox * 4) =
                make_float4(siluf_(a0.x), siluf_(a0.y), siluf_(a1.x), siluf_(a1.y));
            *(float4*)(z_s + t * DI + 64 + ox * 4) =
                make_float4(siluf_(a2.x), siluf_(a2.y), siluf_(a3.x), siluf_(a3.y));
        }
        __syncthreads();
    }

    // ================= output projection: out = z @ out_w^T + out_b =================
    float* wt = wA;  // reuse wA+fz region: [128][256] = 32768 floats
    #pragma unroll 1
    for (int mc = 0; mc < DM; mc += 256) {
        __syncthreads();
        {
            int o    = tid >> 1;          // 0..255
            int half = (tid & 1) * 64;
            const float* src = out_w + (size_t)(mc + o) * DI;
            #pragma unroll
            for (int k4 = 0; k4 < 16; k4++) {
                int k = half + k4 * 4;
                float4 v = *(const float4*)(src + k);
                wt[(k+0)*256 + o] = v.x;
                wt[(k+1)*256 + o] = v.y;
                wt[(k+2)*256 + o] = v.z;
                wt[(k+3)*256 + o] = v.w;
            }
        }
        __syncthreads();
        unsigned long long acc3[2][8];
        #pragma unroll
        for (int g = 0; g < 4; g++) {
            ulonglong2 bb = *(const ulonglong2*)(out_b + mc + g * 64 + ox * 4);
            acc3[0][g*2+0] = bb.x; acc3[0][g*2+1] = bb.y;
            acc3[1][g*2+0] = bb.x; acc3[1][g*2+1] = bb.y;
        }
        #pragma unroll 1
        for (int k = 0; k < DI; k += 4) {
            float4 zr0 = *(const float4*)(z_s + (tA + 0) * DI + k);
            float4 zr1 = *(const float4*)(z_s + (tA + 1) * DI + k);
            #pragma unroll
            for (int kk = 0; kk < 4; kk++) {
                const float* wrow = wt + (k + kk) * 256;
                fma16p(acc3[0], pack2(((const float*)&zr0)[kk]), wrow, ox);
                fma16p(acc3[1], pack2(((const float*)&zr1)[kk]), wrow, ox);
            }
        }
        #pragma unroll
        for (int i = 0; i < 2; i++) {
            float* dst = out + (size_t)(t0 + tA + i) * DM + mc;
            #pragma unroll
            for (int g = 0; g < 4; g++) {
                float2 lo = unpack2(acc3[i][g*2+0]);
                float2 hi = unpack2(acc3[i][g*2+1]);
                *(float4*)(dst + g * 64 + ox * 4) = make_float4(lo.x, lo.y, hi.x, hi.y);
            }
        }
    }
}

#define PRE_SMEM  ((64 * 128 + 128 * 256) * 4)                 /* 160 KB */
#define ITER_SMEM ((64*128 + 128*128 + 128*128 + 64*128 + 64*64 + 64*64) * 4) /* 224 KB */

extern "C" void kernel_launch(void* const* d_in, const int* in_sizes, int n_in,
                              void* d_out, int out_size) {
    const float* x     = (const float*)d_in[0];
    const float* f_w   = (const float*)d_in[1];
    const float* f_b   = (const float*)d_in[2];
    const float* lam_w = (const float*)d_in[3];
    const float* lam_b = (const float*)d_in[4];
    const float* u_w   = (const float*)d_in[5];
    const float* u_b   = (const float*)d_in[6];
    const float* out_w = (const float*)d_in[7];
    const float* out_b = (const float*)d_in[8];
    float* out = (float*)d_out;

    cudaFuncSetAttribute(pre_kernel,  cudaFuncAttributeMaxDynamicSharedMemorySize, PRE_SMEM);
    cudaFuncSetAttribute(iter_kernel, cudaFuncAttributeMaxDynamicSharedMemorySize, ITER_SMEM);

    pre_kernel<<<NBLK, NTHR, PRE_SMEM>>>(x, f_w, f_b, lam_w, lam_b, u_w, u_b);
    iter_kernel<<<NBLK, NTHR, ITER_SMEM>>>(f_w, lam_w, u_w, out_w, out_b, out);
}

// round 10
// speedup vs baseline: 1.6304x; 1.2142x over previous
#include <cuda_runtime.h>

#define SEQ   8192
#define DM    1024
#define DS    64
#define DI    128
#define NIT   50
#define NBLK  128
#define CHUNK 64
#define NTHR  512
#define DZX   1152   /* DI + DM */
#define DZHX  1216   /* DI + DS + DM */
#define PREW  256    /* lam(64) | u(64) | f(128) precomputed x-contributions */

#define ZS    64     /* z_s column stride (tokens contiguous; conflict-free) */
#define LT    68     /* lam_s/u_s token stride (channel-major rows, 16B-aligned) */

// ---- static device scratch (no allocations allowed) ----
__device__ __align__(16) float g_pre[SEQ * PREW];        // 8 MB: x@Wx^T + biases
__device__ __align__(16) float g_agg[NIT * NBLK * 128];  // chunk aggregates (Lam | U)
__device__ int   g_flag[NIT * NBLK];                     // per-iteration readiness flags

__device__ __forceinline__ float sigmoidf_(float a) { return 1.0f / (1.0f + __expf(-a)); }
__device__ __forceinline__ float siluf_(float a)    { return a / (1.0f + __expf(-a)); }

// ---- packed fp32x2 helpers (FFMA2 path; exact fp32 semantics) ----
__device__ __forceinline__ unsigned long long pack2(float v) {
    unsigned long long r;
    asm("mov.b64 %0, {%1, %1};" : "=l"(r) : "r"(__float_as_uint(v)));
    return r;
}
__device__ __forceinline__ void ffma2(unsigned long long& d,
                                      unsigned long long a, unsigned long long b) {
    asm("fma.rn.f32x2 %0, %1, %2, %0;" : "+l"(d) : "l"(a), "l"(b));
}
__device__ __forceinline__ float2 unpack2(unsigned long long v) {
    float2 r;
    unsigned lo, hi;
    asm("mov.b64 {%0, %1}, %2;" : "=r"(lo), "=r"(hi) : "l"(v));
    r.x = __uint_as_float(lo); r.y = __uint_as_float(hi);
    return r;
}

// =====================================================================
// Precompute: g_pre = x @ [lam_wx; u_wx; f_wx]^T + [lam_b; u_b; f_b]
// Also clears the per-launch flags (runs before iter_kernel in-stream).
// =====================================================================
__global__ void __launch_bounds__(NTHR, 1)
pre_kernel(const float* __restrict__ x,
           const float* __restrict__ f_w, const float* __restrict__ f_b,
           const float* __restrict__ lam_w, const float* __restrict__ lam_b,
           const float* __restrict__ u_w, const float* __restrict__ u_b)
{
    for (int i = threadIdx.x + blockIdx.x * NTHR; i < NIT * NBLK; i += gridDim.x * NTHR)
        g_flag[i] = 0;

    extern __shared__ float sm[];
    float* xs = sm;            // [64][128]
    float* wt = sm + 64 * 128; // [128][256] k-major

    const int tid = threadIdx.x;
    const int t0 = blockIdx.x * CHUNK;
    const int ox = tid & 15;       // 16 output groups of 16
    const int ty = tid >> 4;       // 32 token groups of 2
    const int tA = ty * 2;

    unsigned long long acc[2][8];
    #pragma unroll
    for (int i = 0; i < 2; i++)
        #pragma unroll
        for (int j = 0; j < 8; j++) acc[i][j] = 0ull;

    const int o    = tid >> 1;
    const int half = (tid & 1) * 64;
    const float* wsrc;
    if (o < 64)       wsrc = lam_w + o * DZX + DI;
    else if (o < 128) wsrc = u_w + (o - 64) * DZX + DI;
    else              wsrc = f_w + (o - 128) * DZHX + DI + DS;

    #pragma unroll 1
    for (int kt = 0; kt < DM; kt += 128) {
        __syncthreads();
        for (int i = tid; i < 64 * 32; i += NTHR) {
            int r = i >> 5, c4 = (i & 31) << 2;
            *(float4*)(xs + r * 128 + c4) = *(const float4*)(x + (t0 + r) * DM + kt + c4);
        }
        #pragma unroll
        for (int k4 = 0; k4 < 16; k4++) {
            int k = half + k4 * 4;
            float4 v = *(const float4*)(wsrc + kt + k);
            wt[(k + 0) * 256 + o] = v.x;
            wt[(k + 1) * 256 + o] = v.y;
            wt[(k + 2) * 256 + o] = v.z;
            wt[(k + 3) * 256 + o] = v.w;
        }
        __syncthreads();
        #pragma unroll 1
        for (int k = 0; k < 128; k += 4) {
            float4 zr0 = *(const float4*)(xs + (tA + 0) * 128 + k);
            float4 zr1 = *(const float4*)(xs + (tA + 1) * 128 + k);
            #pragma unroll
            for (int kk = 0; kk < 4; kk++) {
                const float* wrow = wt + (k + kk) * 256;
                unsigned long long z0 = pack2(((const float*)&zr0)[kk]);
                unsigned long long z1 = pack2(((const float*)&zr1)[kk]);
                #pragma unroll
                for (int g = 0; g < 4; g++) {
                    ulonglong2 w = *(const ulonglong2*)(wrow + g * 64 + ox * 4);
                    ffma2(acc[0][g*2+0], z0, w.x); ffma2(acc[0][g*2+1], z0, w.y);
                    ffma2(acc[1][g*2+0], z1, w.x); ffma2(acc[1][g*2+1], z1, w.y);
                }
            }
        }
    }
    #pragma unroll
    for (int i = 0; i < 2; i++) {
        float* dst = g_pre + (size_t)(t0 + tA + i) * PREW;
        #pragma unroll
        for (int g = 0; g < 4; g++) {
            float2 lo = unpack2(acc[i][g*2+0]);
            float2 hi = unpack2(acc[i][g*2+1]);
            int o0 = g * 64 + ox * 4;
            float b0, b1, b2, b3;
            if (o0 < 64)       { b0=lam_b[o0]; b1=lam_b[o0+1]; b2=lam_b[o0+2]; b3=lam_b[o0+3]; }
            else if (o0 < 128) { b0=u_b[o0-64]; b1=u_b[o0-63]; b2=u_b[o0-62]; b3=u_b[o0-61]; }
            else               { b0=f_b[o0-128]; b1=f_b[o0-127]; b2=f_b[o0-126]; b3=f_b[o0-125]; }
            *(float4*)(dst + o0) = make_float4(lo.x + b0, lo.y + b1, hi.x + b2, hi.y + b3);
        }
    }
}

// =====================================================================
// Persistent kernel: 50 fixed-point iterations + output projection.
// Fused GEMM [lam|u|fz]@z with fz-accumulators held in registers across
// the scan; z_s column-major (tokens contiguous); lam/u channel-major.
// =====================================================================
__global__ void __launch_bounds__(NTHR, 1)
iter_kernel(const float* __restrict__ f_w,
            const float* __restrict__ lam_w,
            const float* __restrict__ u_w,
            const float* __restrict__ out_w,
            const float* __restrict__ out_b,
            float* __restrict__ out)
{
    extern __shared__ float sm[];
    float* z_s   = sm;                  // [128 k][ZS]   column-major z (tokens contiguous)
    float* wC    = z_s + 128 * ZS;      // [128 k][256 o]  lam(64)|u(64)|fz(128)
    float* fh    = wC + 128 * 256;      // [64 c][128 o]   f_wh c-major
    float* lam_s = fh + 64 * 128;       // [64 c][LT t]    channel-major
    float* u_s   = lam_s + 64 * LT;     // [64 c][LT t]    channel-major

    const int tid = threadIdx.x;
    const int b   = blockIdx.x;
    const int t0  = b * CHUNK;
    const int ox  = tid >> 4;           // 0..31 output group (half-warp uniform)
    const int ty  = tid & 15;           // 16 token groups of 4 (in lanes)
    const int tA  = ty * 4;

    // ---- stage weights transposed (once) ----
    {
        int o    = tid >> 1;            // 0..255
        int half = (tid & 1) * 64;
        const float* src;
        if (o < 64)       src = lam_w + o * DZX;
        else if (o < 128) src = u_w + (o - 64) * DZX;
        else              src = f_w + (o - 128) * DZHX;
        #pragma unroll
        for (int k4 = 0; k4 < 16; k4++) {
            int k = half + k4 * 4;
            float4 v = *(const float4*)(src + k);
            wC[(k+0)*256 + o] = v.x; wC[(k+1)*256 + o] = v.y;
            wC[(k+2)*256 + o] = v.z; wC[(k+3)*256 + o] = v.w;
        }
    }
    {
        int o    = tid >> 2;            // 0..127
        int part = tid & 3;
        const float* sF = f_w + o * DZHX + DI;
        #pragma unroll
        for (int c4 = 0; c4 < 4; c4++) {
            int c = part * 16 + c4 * 4;
            float4 f = *(const float4*)(sF + c);
            fh[(c+0)*128 + o] = f.x; fh[(c+1)*128 + o] = f.y;
            fh[(c+2)*128 + o] = f.z; fh[(c+3)*128 + o] = f.w;
        }
    }
    for (int i = tid; i < 128 * ZS; i += NTHR) z_s[i] = 0.f;
    __syncthreads();

    #pragma unroll 1
    for (int it = 0; it < NIT; ++it) {
        // ================= G1: [lam|u|fz] @ z  (fused) =================
        unsigned long long acc_lo[4][2];   // 4 tokens x 4 lam/u outputs
        unsigned long long acc_hi[4][2];   // 4 tokens x 4 fz outputs (live thru scan)
        #pragma unroll
        for (int i = 0; i < 4; i++) {
            const float* pr = g_pre + (size_t)(t0 + tA + i) * PREW;
            ulonglong2 a = *(const ulonglong2*)(pr + ox * 4);
            ulonglong2 h = *(const ulonglong2*)(pr + 128 + ox * 4);
            acc_lo[i][0] = a.x; acc_lo[i][1] = a.y;
            acc_hi[i][0] = h.x; acc_hi[i][1] = h.y;
        }
        #pragma unroll 4
        for (int k = 0; k < DI; k++) {
            float4 zc = *(const float4*)(z_s + k * ZS + tA);
            ulonglong2 wl = *(const ulonglong2*)(wC + k * 256 + ox * 4);
            ulonglong2 wh = *(const ulonglong2*)(wC + k * 256 + 128 + ox * 4);
            #pragma unroll
            for (int i = 0; i < 4; i++) {
                unsigned long long zz = pack2(((const float*)&zc)[i]);
                ffma2(acc_lo[i][0], zz, wl.x); ffma2(acc_lo[i][1], zz, wl.y);
                ffma2(acc_hi[i][0], zz, wh.x); ffma2(acc_hi[i][1], zz, wh.y);
            }
        }
        // store lam (warps 0-7) / u (warps 8-15) transposed to channel-major
        {
            float v[4][4];                 // v[channel j][token i]
            #pragma unroll
            for (int i = 0; i < 4; i++) {
                float2 a0 = unpack2(acc_lo[i][0]), a1 = unpack2(acc_lo[i][1]);
                v[0][i] = a0.x; v[1][i] = a0.y; v[2][i] = a1.x; v[3][i] = a1.y;
            }
            if (ox < 16) {
                #pragma unroll
                for (int j = 0; j < 4; j++)
                    *(float4*)(lam_s + (ox * 4 + j) * LT + tA) =
                        make_float4(sigmoidf_(v[j][0]), sigmoidf_(v[j][1]),
                                    sigmoidf_(v[j][2]), sigmoidf_(v[j][3]));
            } else {
                #pragma unroll
                for (int j = 0; j < 4; j++)
                    *(float4*)(u_s + ((ox - 16) * 4 + j) * LT + tA) =
                        make_float4(v[j][0], v[j][1], v[j][2], v[j][3]);
            }
        }
        __syncthreads();

        // ===== local scan + publish aggregate; 128 threads pre-spin =====
        if (tid < DS) {
            float* lr = lam_s + tid * LT;
            float* ur = u_s + tid * LT;
            float P = 1.f, H = 0.f;
            #pragma unroll 8
            for (int t = 0; t < CHUNK; t++) {
                float l  = lr[t];
                float uu = ur[t];
                H = fmaf(l, H, uu);
                P *= l;
                lr[t] = P;               // prefix product
                ur[t] = H;               // local inclusive h
            }
            float* ag = g_agg + (size_t)(it * NBLK + b) * 128;
            ag[tid]      = P;
            ag[tid + 64] = H;
            __threadfence();
            asm volatile("bar.sync 1, 64;");
            if (tid == 0)
                *(volatile int*)(g_flag + it * NBLK + b) = 1;
        } else if (tid < 64 + NBLK) {
            int j = tid - 64;
            if (j < b) {
                volatile int* fl = g_flag + it * NBLK + j;
                while (*fl == 0) { }
            }
        }
        __syncthreads();

        // ================= lookback fold + apply + shift =================
        if (tid < DS) {
            int c = tid;
            float h = 0.f;
            const float* ag = g_agg + (size_t)it * NBLK * 128 + c;
            #pragma unroll 4
            for (int j = 0; j < b; j++)
                h = fmaf(ag[j * 128], h, ag[j * 128 + 64]);
            float* lr = lam_s + c * LT;
            float* ur = u_s + c * LT;
            float prev = h;
            #pragma unroll 8
            for (int t = 0; t < CHUNK; t++) {
                float P  = lr[t];
                float Hl = ur[t];
                float hg = fmaf(P, h, Hl);
                ur[t] = prev;            // shifted h used at token t
                prev = hg;
            }
        }
        __syncthreads();

        // ================= G2: acc_hi += fh @ h;  z = silu(acc_hi) =================
        #pragma unroll 2
        for (int c = 0; c < DS; c += 4) {
            float4 hc[4];                 // hc[cc] = 4 tokens of channel c+cc
            #pragma unroll
            for (int cc = 0; cc < 4; cc++)
                hc[cc] = *(const float4*)(u_s + (c + cc) * LT + tA);
            #pragma unroll
            for (int cc = 0; cc < 4; cc++) {
                ulonglong2 w = *(const ulonglong2*)(fh + (c + cc) * 128 + ox * 4);
                #pragma unroll
                for (int i = 0; i < 4; i++) {
                    unsigned long long hh = pack2(((const float*)&hc[cc])[i]);
                    ffma2(acc_hi[i][0], hh, w.x);
                    ffma2(acc_hi[i][1], hh, w.y);
                }
            }
        }
        // silu -> z_s (column-major: 4 cols x 4 tokens)
        {
            float v[4][4];
            #pragma unroll
            for (int i = 0; i < 4; i++) {
                float2 a0 = unpack2(acc_hi[i][0]), a1 = unpack2(acc_hi[i][1]);
                v[i][0] = siluf_(a0.x); v[i][1] = siluf_(a0.y);
                v[i][2] = siluf_(a1.x); v[i][3] = siluf_(a1.y);
            }
            #pragma unroll
            for (int j = 0; j < 4; j++)
                *(float4*)(z_s + (ox * 4 + j) * ZS + tA) =
                    make_float4(v[0][j], v[1][j], v[2][j], v[3][j]);
        }
        __syncthreads();
    }

    // ================= output projection: out = z @ out_w^T + out_b =================
    float* wt = wC;  // reuse [128 k][256 o]
    #pragma unroll 1
    for (int mc = 0; mc < DM; mc += 256) {
        __syncthreads();
        {
            int o    = tid >> 1;
            int half = (tid & 1) * 64;
            const float* src = out_w + (size_t)(mc + o) * DI;
            #pragma unroll
            for (int k4 = 0; k4 < 16; k4++) {
                int k = half + k4 * 4;
                float4 v = *(const float4*)(src + k);
                wt[(k+0)*256 + o] = v.x; wt[(k+1)*256 + o] = v.y;
                wt[(k+2)*256 + o] = v.z; wt[(k+3)*256 + o] = v.w;
            }
        }
        __syncthreads();
        unsigned long long acc3[4][4];     // 4 tokens x 8 outputs
        {
            ulonglong2 b0 = *(const ulonglong2*)(out_b + mc + ox * 8);
            ulonglong2 b1 = *(const ulonglong2*)(out_b + mc + ox * 8 + 4);
            #pragma unroll
            for (int i = 0; i < 4; i++) {
                acc3[i][0] = b0.x; acc3[i][1] = b0.y;
                acc3[i][2] = b1.x; acc3[i][3] = b1.y;
            }
        }
        #pragma unroll 4
        for (int k = 0; k < DI; k++) {
            float4 zc = *(const float4*)(z_s + k * ZS + tA);
            ulonglong2 w0 = *(const ulonglong2*)(wt + k * 256 + ox * 8);
            ulonglong2 w1 = *(const ulonglong2*)(wt + k * 256 + ox * 8 + 4);
            #pragma unroll
            for (int i = 0; i < 4; i++) {
                unsigned long long zz = pack2(((const float*)&zc)[i]);
                ffma2(acc3[i][0], zz, w0.x); ffma2(acc3[i][1], zz, w0.y);
                ffma2(acc3[i][2], zz, w1.x); ffma2(acc3[i][3], zz, w1.y);
            }
        }
        #pragma unroll
        for (int i = 0; i < 4; i++) {
            float* dst = out + (size_t)(t0 + tA + i) * DM + mc + ox * 8;
            float2 a0 = unpack2(acc3[i][0]), a1 = unpack2(acc3[i][1]);
            float2 a2 = unpack2(acc3[i][2]), a3 = unpack2(acc3[i][3]);
            *(float4*)(dst)     = make_float4(a0.x, a0.y, a1.x, a1.y);
            *(float4*)(dst + 4) = make_float4(a2.x, a2.y, a3.x, a3.y);
        }
    }
}

#define PRE_SMEM  ((64 * 128 + 128 * 256) * 4)                       /* 160 KB */
#define ITER_SMEM ((128*ZS + 128*256 + 64*128 + 2*64*LT) * 4)        /* 226 KB */

extern "C" void kernel_launch(void* const* d_in, const int* in_sizes, int n_in,
                              void* d_out, int out_size) {
    const float* x     = (const float*)d_in[0];
    const float* f_w   = (const float*)d_in[1];
    const float* f_b   = (const float*)d_in[2];
    const float* lam_w = (const float*)d_in[3];
    const float* lam_b = (const float*)d_in[4];
    const float* u_w   = (const float*)d_in[5];
    const float* u_b   = (const float*)d_in[6];
    const float* out_w = (const float*)d_in[7];
    const float* out_b = (const float*)d_in[8];
    float* out = (float*)d_out;

    cudaFuncSetAttribute(pre_kernel,  cudaFuncAttributeMaxDynamicSharedMemorySize, PRE_SMEM);
    cudaFuncSetAttribute(iter_kernel, cudaFuncAttributeMaxDynamicSharedMemorySize, ITER_SMEM);

    pre_kernel<<<NBLK, NTHR, PRE_SMEM>>>(x, f_w, f_b, lam_w, lam_b, u_w, u_b);
    iter_kernel<<<NBLK, NTHR, ITER_SMEM>>>(f_w, lam_w, u_w, out_w, out_b, out);
}